// round 1
// baseline (speedup 1.0000x reference)
#include <cuda_runtime.h>
#include <cstdint>

// Offset-guided top (column) pooling.
// out[b,c,i,j] = max_{0 <= d <= offset[b,i,j], i+d < H} x[b,c,i+d,j]
// Shapes fixed by the problem: B=32, C=64, H=160, W=160, MAX_OFFSET=8.

#define B_ 32
#define C_ 64
#define H_ 160
#define W_ 160
#define NEGF (-3.402823466e38f)

__global__ __launch_bounds__(W_) void top_pool_kernel(
    const float* __restrict__ x,
    const int*   __restrict__ offset,
    float*       __restrict__ out)
{
    const int j  = threadIdx.x;        // 0..159 (column index)
    const int bc = blockIdx.x;         // 0..B*C-1
    const int b  = bc >> 6;            // bc / C_  (C_ = 64)

    const float* xp  = x      + (size_t)bc * (H_ * W_) + j;
    float*       op  = out    + (size_t)bc * (H_ * W_) + j;
    const int*   ofp = offset + (size_t)b  * (H_ * W_) + j;

    // 8-deep register ring: v[k] holds x[i+k, j] at the top of iteration i.
    float v[8];
#pragma unroll
    for (int d = 0; d < 8; d++)
        v[d] = xp[d * W_];             // rows 0..7 always valid (H_ > 7)

#pragma unroll 8
    for (int i = 0; i < H_; i++) {
        const int off = ofp[i * W_];

        // best = prefix_max(v)[off], branch-free select chain.
        float run  = v[0];
        float best = v[0];
#pragma unroll
        for (int d = 1; d < 8; d++) {
            run = fmaxf(run, v[d]);
            if (off >= d) best = run;
        }
        op[i * W_] = best;

        // Slide window down: rotation becomes register renaming under unroll-8.
#pragma unroll
        for (int d = 0; d < 7; d++) v[d] = v[d + 1];
        const int nr = i + 8;
        v[7] = (nr < H_) ? xp[nr * W_] : NEGF;
    }
}

extern "C" void kernel_launch(void* const* d_in, const int* in_sizes, int n_in,
                              void* d_out, int out_size)
{
    const float* x      = (const float*)d_in[0];
    const int*   offset = (const int*)  d_in[1];
    float*       out    = (float*)d_out;

    // One block per (b, c) pair; one thread per column j.
    top_pool_kernel<<<B_ * C_, W_>>>(x, offset, out);
}

// round 2
// speedup vs baseline: 1.3684x; 1.3684x over previous
#include <cuda_runtime.h>
#include <cstdint>

// Offset-guided top (column) pooling.
// out[b,c,i,j] = max_{0 <= d <= offset[b,i,j], i+d < H} x[b,c,i+d,j]
// Shapes fixed: B=32, C=64, H=160, W=160, MAX_OFFSET=8.
//
// R1 strategy: 4 channels per thread at the same (b,j) so the 7 offset
// predicates are computed once and reused; prefix-max select becomes
// predicated FMNMX. H split into 2 chunks of 80 rows -> grid 1024 ~ 1 wave.

#define B_ 32
#define C_ 64
#define H_ 160
#define W_ 160
#define PLANE_ (H_ * W_)
#define CHUNK_ 80
#define NC_ 4
#define NEGF (-3.402823466e38f)

__global__ __launch_bounds__(W_, 6) void top_pool_kernel(
    const float* __restrict__ x,
    const int*   __restrict__ offset,
    float*       __restrict__ out)
{
    const int j    = threadIdx.x;          // column 0..159
    const int half = blockIdx.x & 1;       // H chunk
    const int cg   = (blockIdx.x >> 1) & 15;   // channel group (of 4)
    const int b    = blockIdx.x >> 5;      // batch

    const int h0 = half * CHUNK_;
    const int c0 = cg * NC_;

    const float* xp  = x      + ((size_t)(b * C_ + c0) * H_ + h0) * W_ + j;
    float*       op  = out    + ((size_t)(b * C_ + c0) * H_ + h0) * W_ + j;
    const int*   ofp = offset + ((size_t)b * H_ + h0) * W_ + j;

    // 8-deep register ring per channel: v[c][d] = x[c0+c, h0+i+d, j].
    float v[NC_][8];
#pragma unroll
    for (int c = 0; c < NC_; c++)
#pragma unroll
        for (int d = 0; d < 8; d++)
            v[c][d] = xp[c * PLANE_ + d * W_];    // h0+7 <= 87 < H, always valid

#pragma unroll 4
    for (int i = 0; i < CHUNK_; i++) {
        const int off = ofp[i * W_];              // shared across 4 channels

#pragma unroll
        for (int c = 0; c < NC_; c++) {
            float best = v[c][0];
            // off>=d is monotone in d => predicated running max == prefix_max[off]
#pragma unroll
            for (int d = 1; d < 8; d++)
                if (off >= d) best = fmaxf(best, v[c][d]);
            op[c * PLANE_ + i * W_] = best;
        }

        // Slide window down one row (register renaming under unroll).
        const int nr = h0 + i + 8;
        const bool ok = nr < H_;
#pragma unroll
        for (int c = 0; c < NC_; c++) {
#pragma unroll
            for (int d = 0; d < 7; d++) v[c][d] = v[c][d + 1];
            v[c][7] = ok ? xp[c * PLANE_ + (i + 8) * W_] : NEGF;
        }
    }
}

extern "C" void kernel_launch(void* const* d_in, const int* in_sizes, int n_in,
                              void* d_out, int out_size)
{
    const float* x      = (const float*)d_in[0];
    const int*   offset = (const int*)  d_in[1];
    float*       out    = (float*)d_out;

    // grid = B * (C/4) * 2 halves = 32*16*2 = 1024 blocks, 160 threads each.
    top_pool_kernel<<<B_ * (C_ / NC_) * 2, W_>>>(x, offset, out);
}